// round 13
// baseline (speedup 1.0000x reference)
#include <cuda_runtime.h>
#include <math.h>
#include <stdint.h>

#define NPTS   4096
#define TOTALP 8192          // B*N
#define KNN    20
#define EPSV   1e-5f
#define SLOPEV 0.2f

typedef unsigned long long u64;

// ---------------- scratch (device globals; allocation-free rule) -------------
__device__ float g_feat0[TOTALP * 3];
__device__ float g_xx[TOTALP];
__device__ float g_negd[(size_t)2 * NPTS * NPTS];      // 128 MB distance matrix
__device__ float g_Wst[512 * 128];                     // stacked [W_l ; W_r-W_l]
__device__ float g_UV[(size_t)TOTALP * 512];           // [U | V] per point
__device__ int   g_idx[TOTALP * KNN];
__device__ float g_maxh[(size_t)TOTALP * 256];
__device__ float g_cat[(size_t)TOTALP * 512];          // x1|x2|x3|x4
__device__ float g_h5[(size_t)TOTALP * 1024];
__device__ float g_sum[1024];
__device__ float g_sumsq[1024];
__device__ float g_scale[1024];
__device__ float g_shift[1024];

// ---------------- prep: transpose x (B,3,N)->(B,N,3), squared norms ----------
__global__ void k_prep_in(const float* __restrict__ x) {
    int p = blockIdx.x * 256 + threadIdx.x;
    if (p >= TOTALP) return;
    int b = p >> 12, n = p & (NPTS - 1);
    float a0 = x[((size_t)b * 3 + 0) * NPTS + n];
    float a1 = x[((size_t)b * 3 + 1) * NPTS + n];
    float a2 = x[((size_t)b * 3 + 2) * NPTS + n];
    g_feat0[p * 3 + 0] = a0;
    g_feat0[p * 3 + 1] = a1;
    g_feat0[p * 3 + 2] = a2;
    g_xx[p] = a0 * a0 + a1 * a1 + a2 * a2;
}

// ---------------- build stacked weights: rows [0,O)=W_l, [O,2O)=W_r-W_l ------
__global__ void k_prepw(const float* __restrict__ W, int O, int C) {
    int i = blockIdx.x * 256 + threadIdx.x;
    if (i >= O * C) return;
    int o = i / C, c = i - o * C;
    float wl = W[(size_t)o * 2 * C + c];
    float wr = W[(size_t)o * 2 * C + C + c];
    g_Wst[(size_t)o * C + c]       = wl;
    g_Wst[(size_t)(O + o) * C + c] = wr - wl;
}

// ---------------- generic K-major x K-major GEMM: C[i,j]=sum_c A[i,c]B[j,c] --
// mode 0: plain store.  mode 1: store 2*acc - xx[row] - xx[col] (neg distance)
__global__ __launch_bounds__(256) void k_gemm(
    const float* __restrict__ A, int lda, size_t aStride,
    const float* __restrict__ Bm, int ldb, size_t bStride,
    float* __restrict__ Cm, int ldc, size_t cStride,
    int Kdim, int mode, const float* __restrict__ xx, int xxStride)
{
    int bz = blockIdx.z;
    A  += (size_t)bz * aStride;
    Bm += (size_t)bz * bStride;
    Cm += (size_t)bz * cStride;
    const float* xxb = xx ? (xx + (size_t)bz * xxStride) : nullptr;

    int m0 = blockIdx.y * 64, n0 = blockIdx.x * 64;
    __shared__ float As[16][64];
    __shared__ float Bs[16][64];
    float acc[4][4] = {};
    int tid = threadIdx.x;
    int tx = tid & 15, ty = tid >> 4;

    for (int k0 = 0; k0 < Kdim; k0 += 16) {
        for (int l = tid; l < 1024; l += 256) {
            int r = l >> 4, kk = l & 15;
            int gk = k0 + kk;
            As[kk][r] = (gk < Kdim) ? A[(size_t)(m0 + r) * lda + gk] : 0.f;
            Bs[kk][r] = (gk < Kdim) ? Bm[(size_t)(n0 + r) * ldb + gk] : 0.f;
        }
        __syncthreads();
#pragma unroll
        for (int kk = 0; kk < 16; kk++) {
            float av[4], bv[4];
#pragma unroll
            for (int i = 0; i < 4; i++) av[i] = As[kk][ty * 4 + i];
#pragma unroll
            for (int j = 0; j < 4; j++) bv[j] = Bs[kk][tx * 4 + j];
#pragma unroll
            for (int i = 0; i < 4; i++)
#pragma unroll
                for (int j = 0; j < 4; j++) acc[i][j] += av[i] * bv[j];
        }
        __syncthreads();
    }

#pragma unroll
    for (int i = 0; i < 4; i++) {
        int rr = m0 + ty * 4 + i;
#pragma unroll
        for (int j = 0; j < 4; j++) {
            int cc = n0 + tx * 4 + j;
            float v = acc[i][j];
            if (mode == 1) v = 2.f * v - xxb[rr] - xxb[cc];
            Cm[(size_t)rr * ldc + cc] = v;
        }
    }
}

// ---------------- streaming top-20: one warp per row, registers only ---------
// key = (monotone(value) << 32) | ~j  -> max key = max value, ties: min index.
// Merge keeps head at compile-time slot list[KNN-1]; winner shifts list up.
__global__ __launch_bounds__(256) void k_topk2() {
    int warp = threadIdx.x >> 5, lane = threadIdx.x & 31;
    int p = blockIdx.x * 8 + warp;
    const float* __restrict__ src = g_negd + (size_t)p * NPTS;

    u64 list[KNN];                 // sorted ascending; list[0] = threshold
#pragma unroll
    for (int t = 0; t < KNN; t++) list[t] = 0ULL;

    for (int i = 0; i < NPTS / 32; i++) {
        int j = lane + (i << 5);
        unsigned vb = __float_as_uint(src[j]);
        vb = (vb & 0x80000000u) ? ~vb : (vb | 0x80000000u);
        u64 key = ((u64)vb << 32) | (unsigned)(~j);
        if (key > list[0]) {
            list[0] = key;
#pragma unroll
            for (int t = 0; t < KNN - 1; t++) {
                if (list[t] > list[t + 1]) {
                    u64 tmp = list[t]; list[t] = list[t + 1]; list[t + 1] = tmp;
                } else break;
            }
        }
    }

    // 20 rounds of warp-wide max over per-lane heads (head = list[KNN-1])
    for (int r = 0; r < KNN; r++) {
        u64 head = list[KNN - 1];
        u64 m = head;
#pragma unroll
        for (int s = 16; s; s >>= 1) {
            u64 o = __shfl_xor_sync(0xffffffffu, m, s);
            if (o > m) m = o;
        }
        if (head == m) {           // unique winner: pop my head (shift up)
#pragma unroll
            for (int t = KNN - 1; t > 0; t--) list[t] = list[t - 1];
            list[0] = 0ULL;
        }
        if (lane == 0)
            g_idx[(size_t)p * KNN + r] = (int)((~(unsigned)m) & (NPTS - 1));
    }
}

// ---------------- zero the per-channel stat accumulators ---------------------
__global__ void k_zero() {
    int i = blockIdx.x * 256 + threadIdx.x;
    if (i < 1024) { g_sum[i] = 0.f; g_sumsq[i] = 0.f; }
}

// ---------------- gather neighbors, max over k, accumulate BN stats ----------
// h[b,n,k,o] = U[idx,o] + V[n,o].  thread = channel o; block strides points.
__global__ void k_gather(int O) {
    int o = threadIdx.x;
    int O2 = 2 * O;
    float s = 0.f, s2 = 0.f;
    for (int p = blockIdx.x; p < TOTALP; p += gridDim.x) {
        int base = p & ~(NPTS - 1);
        float v = g_UV[(size_t)p * O2 + O + o];
        const int* ip = g_idx + (size_t)p * KNN;
        float mx = -INFINITY;
#pragma unroll
        for (int k = 0; k < KNN; k++) {
            int j = ip[k];
            float u = g_UV[(size_t)(base + j) * O2 + o];
            float h = u + v;
            mx = fmaxf(mx, h);
            s += h; s2 += h * h;
        }
        g_maxh[(size_t)p * O + o] = mx;
    }
    atomicAdd(&g_sum[o], s);
    atomicAdd(&g_sumsq[o], s2);
}

// ---------------- finalize BN affine params ----------------------------------
__global__ void k_bnparam(const float* __restrict__ g, const float* __restrict__ b,
                          float invcnt, int O) {
    int o = blockIdx.x * 256 + threadIdx.x;
    if (o >= O) return;
    float m = g_sum[o] * invcnt;
    float v = g_sumsq[o] * invcnt - m * m;
    float sc = g[o] * rsqrtf(v + EPSV);
    g_scale[o] = sc;
    g_shift[o] = b[o] - m * sc;
}

// ---------------- normalize+leaky into cat slice, next-layer norms -----------
__global__ void k_norm(int O, int catoff) {
    __shared__ float red[256];
    int p = blockIdx.x, o = threadIdx.x;
    float v = g_maxh[(size_t)p * O + o] * g_scale[o] + g_shift[o];
    v = v > 0.f ? v : SLOPEV * v;
    g_cat[(size_t)p * 512 + catoff + o] = v;
    red[o] = v * v;
    __syncthreads();
    for (int s = blockDim.x >> 1; s > 0; s >>= 1) {
        if (o < s) red[o] += red[o + s];
        __syncthreads();
    }
    if (o == 0) g_xx[p] = red[0];
}

// ---------------- column stats of h5 (1024 channels over 8192 points) --------
__global__ void k_colstats() {
    int tid = threadIdx.x;
    float s[4] = {0, 0, 0, 0}, s2[4] = {0, 0, 0, 0};
    for (int p = blockIdx.x; p < TOTALP; p += gridDim.x) {
        const float* r = g_h5 + (size_t)p * 1024;
#pragma unroll
        for (int q = 0; q < 4; q++) {
            float v = r[tid + (q << 8)];
            s[q] += v; s2[q] += v * v;
        }
    }
#pragma unroll
    for (int q = 0; q < 4; q++) {
        atomicAdd(&g_sum[tid + (q << 8)], s[q]);
        atomicAdd(&g_sumsq[tid + (q << 8)], s2[q]);
    }
}

// ---------------- BN + leaky + transpose to (B,1024,N) -----------------------
__global__ void k_out(float* __restrict__ out) {
    __shared__ float t[32][33];
    int n0 = blockIdx.x * 32, o0 = blockIdx.y * 32, b = blockIdx.z;
    for (int i = threadIdx.y; i < 32; i += 8) {
        int n = n0 + i;
        int o = o0 + threadIdx.x;
        float v = g_h5[((size_t)(b * NPTS + n)) * 1024 + o];
        v = v * g_scale[o] + g_shift[o];
        v = v > 0.f ? v : SLOPEV * v;
        t[i][threadIdx.x] = v;
    }
    __syncthreads();
    for (int i = threadIdx.y; i < 32; i += 8) {
        int o = o0 + i;
        int n = n0 + threadIdx.x;
        out[(size_t)b * 1024 * NPTS + (size_t)o * NPTS + n] = t[threadIdx.x][i];
    }
}

// ---------------- driver ------------------------------------------------------
extern "C" void kernel_launch(void* const* d_in, const int* in_sizes, int n_in,
                              void* d_out, int out_size) {
    (void)in_sizes; (void)n_in; (void)out_size;
    const float* x = (const float*)d_in[0];
    const float* Wl[5] = {(const float*)d_in[1], (const float*)d_in[4],
                          (const float*)d_in[7], (const float*)d_in[10],
                          (const float*)d_in[13]};
    const float* gl[5] = {(const float*)d_in[2], (const float*)d_in[5],
                          (const float*)d_in[8], (const float*)d_in[11],
                          (const float*)d_in[14]};
    const float* bl[5] = {(const float*)d_in[3], (const float*)d_in[6],
                          (const float*)d_in[9], (const float*)d_in[12],
                          (const float*)d_in[15]};

    float *feat0, *xxp, *negd, *wst, *uv, *cat, *h5;
    cudaGetSymbolAddress((void**)&feat0, g_feat0);
    cudaGetSymbolAddress((void**)&xxp,   g_xx);
    cudaGetSymbolAddress((void**)&negd,  g_negd);
    cudaGetSymbolAddress((void**)&wst,   g_Wst);
    cudaGetSymbolAddress((void**)&uv,    g_UV);
    cudaGetSymbolAddress((void**)&cat,   g_cat);
    cudaGetSymbolAddress((void**)&h5,    g_h5);

    k_prep_in<<<TOTALP / 256, 256>>>(x);

    const int Cs[4]   = {3, 64, 64, 128};
    const int Os[4]   = {64, 64, 128, 256};
    const int offs[4] = {0, 64, 128, 256};
    const float* inA = feat0;
    int lda = 3;

    for (int l = 0; l < 4; l++) {
        int C = Cs[l], O = Os[l];
        k_prepw<<<(O * C + 255) / 256, 256>>>(Wl[l], O, C);
        {   // U|V = X @ [W_l ; W_r - W_l]^T  (M=8192, N=2O, K=C)
            dim3 g(2 * O / 64, TOTALP / 64, 1);
            k_gemm<<<g, 256>>>(inA, lda, 0, wst, C, 0, uv, 2 * O, 0,
                               C, 0, nullptr, 0);
        }
        {   // neg_d = 2*X@X^T - xx_i - xx_j, per batch
            dim3 g(NPTS / 64, NPTS / 64, 2);
            k_gemm<<<g, 256>>>(inA, lda, (size_t)NPTS * lda,
                               inA, lda, (size_t)NPTS * lda,
                               negd, NPTS, (size_t)NPTS * NPTS,
                               C, 1, xxp, NPTS);
        }
        k_topk2<<<TOTALP / 8, 256>>>();
        k_zero<<<4, 256>>>();
        k_gather<<<2048, O>>>(O);
        k_bnparam<<<(O + 255) / 256, 256>>>(gl[l], bl[l],
                                            1.0f / (float)(TOTALP * KNN), O);
        k_norm<<<TOTALP, O>>>(O, offs[l]);
        inA = cat + offs[l];
        lda = 512;
    }

    {   // h5 = cat @ W5^T  (M=8192, N=1024, K=512)
        dim3 g(1024 / 64, TOTALP / 64, 1);
        k_gemm<<<g, 256>>>(cat, 512, 0, Wl[4], 512, 0, h5, 1024, 0,
                           512, 0, nullptr, 0);
    }
    k_zero<<<4, 256>>>();
    k_colstats<<<256, 256>>>();
    k_bnparam<<<4, 256>>>(gl[4], bl[4], 1.0f / (float)TOTALP, 1024);
    {
        dim3 g(NPTS / 32, 1024 / 32, 2);
        k_out<<<g, dim3(32, 8)>>>((float*)d_out);
    }
}

// round 16
// speedup vs baseline: 2.2807x; 2.2807x over previous
#include <cuda_runtime.h>
#include <math.h>
#include <stdint.h>

#define NPTS   4096
#define TOTALP 8192          // B*N
#define KNN    20
#define EPSV   1e-5f
#define SLOPEV 0.2f

// ---------------- scratch (device globals; allocation-free rule) -------------
__device__ float g_feat0[TOTALP * 3];
__device__ float g_xx[TOTALP];
__device__ float g_negd[(size_t)2 * NPTS * NPTS];      // 128 MB distance matrix
__device__ float g_Wst[512 * 128];                     // stacked [W_l ; W_r-W_l]
__device__ float g_UV[(size_t)TOTALP * 512];           // [U | V] per point
__device__ int   g_idx[TOTALP * KNN];
__device__ float g_maxh[(size_t)TOTALP * 256];
__device__ float g_cat[(size_t)TOTALP * 512];          // x1|x2|x3|x4
__device__ float g_h5[(size_t)TOTALP * 1024];
__device__ float g_sum[1024];
__device__ float g_sumsq[1024];
__device__ float g_scale[1024];
__device__ float g_shift[1024];

// ---------------- prep: transpose x (B,3,N)->(B,N,3), squared norms ----------
__global__ void k_prep_in(const float* __restrict__ x) {
    int p = blockIdx.x * 256 + threadIdx.x;
    if (p >= TOTALP) return;
    int b = p >> 12, n = p & (NPTS - 1);
    float a0 = x[((size_t)b * 3 + 0) * NPTS + n];
    float a1 = x[((size_t)b * 3 + 1) * NPTS + n];
    float a2 = x[((size_t)b * 3 + 2) * NPTS + n];
    g_feat0[p * 3 + 0] = a0;
    g_feat0[p * 3 + 1] = a1;
    g_feat0[p * 3 + 2] = a2;
    g_xx[p] = a0 * a0 + a1 * a1 + a2 * a2;
}

// ---------------- build stacked weights: rows [0,O)=W_l, [O,2O)=W_r-W_l ------
__global__ void k_prepw(const float* __restrict__ W, int O, int C) {
    int i = blockIdx.x * 256 + threadIdx.x;
    if (i >= O * C) return;
    int o = i / C, c = i - o * C;
    float wl = W[(size_t)o * 2 * C + c];
    float wr = W[(size_t)o * 2 * C + C + c];
    g_Wst[(size_t)o * C + c]       = wl;
    g_Wst[(size_t)(O + o) * C + c] = wr - wl;
}

// ---------------- 128x64x16 SGEMM, 8x4 microtile: C[i,j]=sum_c A[i,c]B[j,c] --
// Both operands K-major, exact fp32, serial ascending-k accumulation.
// mode 0: plain. mode 1: 2*acc - xx[row] - xx[col].
__global__ __launch_bounds__(256) void k_gemm3(
    const float* __restrict__ A, int lda, size_t aStride,
    const float* __restrict__ Bm, int ldb, size_t bStride,
    float* __restrict__ Cm, int ldc, size_t cStride,
    int Kdim, int mode, const float* __restrict__ xx, int xxStride)
{
    int bz = blockIdx.z;
    A  += (size_t)bz * aStride;
    Bm += (size_t)bz * bStride;
    Cm += (size_t)bz * cStride;
    const float* xxb = xx ? (xx + (size_t)bz * xxStride) : nullptr;

    int m0 = blockIdx.y * 128, n0 = blockIdx.x * 64;
    __shared__ float As[16][132];   // 132*4B = 33*16B: float4-aligned rows
    __shared__ float Bs[16][68];    // 68*4B = 17*16B
    float acc[8][4] = {};
    int tid = threadIdx.x;
    int tx = tid & 15, ty = tid >> 4;

    for (int k0 = 0; k0 < Kdim; k0 += 16) {
#pragma unroll
        for (int l = 0; l < 8; l++) {           // A tile: 128 rows x 16 k
            int e = tid + l * 256;
            int r = e >> 4, kk = e & 15;
            int gk = k0 + kk;
            As[kk][r] = (gk < Kdim) ? A[(size_t)(m0 + r) * lda + gk] : 0.f;
        }
#pragma unroll
        for (int l = 0; l < 4; l++) {           // B tile: 64 rows x 16 k
            int e = tid + l * 256;
            int r = e >> 4, kk = e & 15;
            int gk = k0 + kk;
            Bs[kk][r] = (gk < Kdim) ? Bm[(size_t)(n0 + r) * ldb + gk] : 0.f;
        }
        __syncthreads();
#pragma unroll
        for (int kk = 0; kk < 16; kk++) {
            float4 a0 = *(const float4*)&As[kk][ty * 8];
            float4 a1 = *(const float4*)&As[kk][ty * 8 + 4];
            float4 b0 = *(const float4*)&Bs[kk][tx * 4];
            float av[8] = {a0.x, a0.y, a0.z, a0.w, a1.x, a1.y, a1.z, a1.w};
            float bv[4] = {b0.x, b0.y, b0.z, b0.w};
#pragma unroll
            for (int i = 0; i < 8; i++)
#pragma unroll
                for (int j = 0; j < 4; j++) acc[i][j] += av[i] * bv[j];
        }
        __syncthreads();
    }

#pragma unroll
    for (int i = 0; i < 8; i++) {
        int rr = m0 + ty * 8 + i;
        float xr = (mode == 1) ? xxb[rr] : 0.f;
#pragma unroll
        for (int j = 0; j < 4; j++) {
            int cc = n0 + tx * 4 + j;
            float v = acc[i][j];
            if (mode == 1) v = 2.f * v - xr - xxb[cc];
            Cm[(size_t)rr * ldc + cc] = v;
        }
    }
}

// ---------------- top-20 per row (value-major, smaller-index tie-break) ------
__global__ __launch_bounds__(256) void k_topk() {
    __shared__ float row[NPTS];
    __shared__ float rv[256];
    __shared__ int   ri[256];
    int p = blockIdx.x;
    int tid = threadIdx.x;
    const float* src = g_negd + (size_t)p * NPTS;
    for (int i = tid; i < NPTS; i += 256) row[i] = src[i];
    __syncthreads();

    for (int r = 0; r < KNN; r++) {
        float bv = -INFINITY;
        int bi = NPTS;
        for (int i = tid; i < NPTS; i += 256) {
            float v = row[i];
            if (v > bv) { bv = v; bi = i; }   // ascending scan keeps smallest i on ties
        }
        rv[tid] = bv; ri[tid] = bi;
        __syncthreads();
        for (int s = 128; s > 0; s >>= 1) {
            if (tid < s) {
                float v2 = rv[tid + s]; int i2 = ri[tid + s];
                if (v2 > rv[tid] || (v2 == rv[tid] && i2 < ri[tid])) {
                    rv[tid] = v2; ri[tid] = i2;
                }
            }
            __syncthreads();
        }
        int w = ri[0];
        if (tid == 0) {
            g_idx[(size_t)p * KNN + r] = w;
            row[w] = -INFINITY;
        }
        __syncthreads();
    }
}

// ---------------- zero the per-channel stat accumulators ---------------------
__global__ void k_zero() {
    int i = blockIdx.x * 256 + threadIdx.x;
    if (i < 1024) { g_sum[i] = 0.f; g_sumsq[i] = 0.f; }
}

// ---------------- gather neighbors, max over k, accumulate BN stats ----------
// h[b,n,k,o] = U[idx,o] + V[n,o].  thread = channel o; block strides points.
__global__ void k_gather(int O) {
    int o = threadIdx.x;
    int O2 = 2 * O;
    float s = 0.f, s2 = 0.f;
    for (int p = blockIdx.x; p < TOTALP; p += gridDim.x) {
        int base = p & ~(NPTS - 1);
        float v = g_UV[(size_t)p * O2 + O + o];
        const int* ip = g_idx + (size_t)p * KNN;
        float mx = -INFINITY;
#pragma unroll
        for (int k = 0; k < KNN; k++) {
            int j = ip[k];
            float u = g_UV[(size_t)(base + j) * O2 + o];
            float h = u + v;
            mx = fmaxf(mx, h);
            s += h; s2 += h * h;
        }
        g_maxh[(size_t)p * O + o] = mx;
    }
    atomicAdd(&g_sum[o], s);
    atomicAdd(&g_sumsq[o], s2);
}

// ---------------- finalize BN affine params ----------------------------------
__global__ void k_bnparam(const float* __restrict__ g, const float* __restrict__ b,
                          float invcnt, int O) {
    int o = blockIdx.x * 256 + threadIdx.x;
    if (o >= O) return;
    float m = g_sum[o] * invcnt;
    float v = g_sumsq[o] * invcnt - m * m;
    float sc = g[o] * rsqrtf(v + EPSV);
    g_scale[o] = sc;
    g_shift[o] = b[o] - m * sc;
}

// ---------------- normalize+leaky into cat slice, next-layer norms -----------
__global__ void k_norm(int O, int catoff) {
    __shared__ float red[256];
    int p = blockIdx.x, o = threadIdx.x;
    float v = g_maxh[(size_t)p * O + o] * g_scale[o] + g_shift[o];
    v = v > 0.f ? v : SLOPEV * v;
    g_cat[(size_t)p * 512 + catoff + o] = v;
    red[o] = v * v;
    __syncthreads();
    for (int s = blockDim.x >> 1; s > 0; s >>= 1) {
        if (o < s) red[o] += red[o + s];
        __syncthreads();
    }
    if (o == 0) g_xx[p] = red[0];
}

// ---------------- column stats of h5 (1024 channels over 8192 points) --------
__global__ void k_colstats() {
    int tid = threadIdx.x;
    float s[4] = {0, 0, 0, 0}, s2[4] = {0, 0, 0, 0};
    for (int p = blockIdx.x; p < TOTALP; p += gridDim.x) {
        const float* r = g_h5 + (size_t)p * 1024;
#pragma unroll
        for (int q = 0; q < 4; q++) {
            float v = r[tid + (q << 8)];
            s[q] += v; s2[q] += v * v;
        }
    }
#pragma unroll
    for (int q = 0; q < 4; q++) {
        atomicAdd(&g_sum[tid + (q << 8)], s[q]);
        atomicAdd(&g_sumsq[tid + (q << 8)], s2[q]);
    }
}

// ---------------- BN + leaky + transpose to (B,1024,N) -----------------------
__global__ void k_out(float* __restrict__ out) {
    __shared__ float t[32][33];
    int n0 = blockIdx.x * 32, o0 = blockIdx.y * 32, b = blockIdx.z;
    for (int i = threadIdx.y; i < 32; i += 8) {
        int n = n0 + i;
        int o = o0 + threadIdx.x;
        float v = g_h5[((size_t)(b * NPTS + n)) * 1024 + o];
        v = v * g_scale[o] + g_shift[o];
        v = v > 0.f ? v : SLOPEV * v;
        t[i][threadIdx.x] = v;
    }
    __syncthreads();
    for (int i = threadIdx.y; i < 32; i += 8) {
        int o = o0 + i;
        int n = n0 + threadIdx.x;
        out[(size_t)b * 1024 * NPTS + (size_t)o * NPTS + n] = t[threadIdx.x][i];
    }
}

// ---------------- driver ------------------------------------------------------
extern "C" void kernel_launch(void* const* d_in, const int* in_sizes, int n_in,
                              void* d_out, int out_size) {
    (void)in_sizes; (void)n_in; (void)out_size;
    const float* x = (const float*)d_in[0];
    const float* Wl[5] = {(const float*)d_in[1], (const float*)d_in[4],
                          (const float*)d_in[7], (const float*)d_in[10],
                          (const float*)d_in[13]};
    const float* gl[5] = {(const float*)d_in[2], (const float*)d_in[5],
                          (const float*)d_in[8], (const float*)d_in[11],
                          (const float*)d_in[14]};
    const float* bl[5] = {(const float*)d_in[3], (const float*)d_in[6],
                          (const float*)d_in[9], (const float*)d_in[12],
                          (const float*)d_in[15]};

    float *feat0, *xxp, *negd, *wst, *uv, *cat, *h5;
    cudaGetSymbolAddress((void**)&feat0, g_feat0);
    cudaGetSymbolAddress((void**)&xxp,   g_xx);
    cudaGetSymbolAddress((void**)&negd,  g_negd);
    cudaGetSymbolAddress((void**)&wst,   g_Wst);
    cudaGetSymbolAddress((void**)&uv,    g_UV);
    cudaGetSymbolAddress((void**)&cat,   g_cat);
    cudaGetSymbolAddress((void**)&h5,    g_h5);

    k_prep_in<<<TOTALP / 256, 256>>>(x);

    const int Cs[4]   = {3, 64, 64, 128};
    const int Os[4]   = {64, 64, 128, 256};
    const int offs[4] = {0, 64, 128, 256};
    const float* inA = feat0;
    int lda = 3;

    for (int l = 0; l < 4; l++) {
        int C = Cs[l], O = Os[l];
        k_prepw<<<(O * C + 255) / 256, 256>>>(Wl[l], O, C);
        {   // U|V = X @ [W_l ; W_r - W_l]^T  (M=8192, N=2O, K=C)
            dim3 g(2 * O / 64, TOTALP / 128, 1);
            k_gemm3<<<g, 256>>>(inA, lda, 0, wst, C, 0, uv, 2 * O, 0,
                                C, 0, nullptr, 0);
        }
        {   // neg_d = 2*X@X^T - xx_i - xx_j, per batch
            dim3 g(NPTS / 64, NPTS / 128, 2);
            k_gemm3<<<g, 256>>>(inA, lda, (size_t)NPTS * lda,
                                inA, lda, (size_t)NPTS * lda,
                                negd, NPTS, (size_t)NPTS * NPTS,
                                C, 1, xxp, NPTS);
        }
        k_topk<<<TOTALP, 256>>>();
        k_zero<<<4, 256>>>();
        k_gather<<<2048, O>>>(O);
        k_bnparam<<<(O + 255) / 256, 256>>>(gl[l], bl[l],
                                            1.0f / (float)(TOTALP * KNN), O);
        k_norm<<<TOTALP, O>>>(O, offs[l]);
        inA = cat + offs[l];
        lda = 512;
    }

    {   // h5 = cat @ W5^T  (M=8192, N=1024, K=512)
        dim3 g(1024 / 64, TOTALP / 128, 1);
        k_gemm3<<<g, 256>>>(cat, 512, 0, Wl[4], 512, 0, h5, 1024, 0,
                            512, 0, nullptr, 0);
    }
    k_zero<<<4, 256>>>();
    k_colstats<<<256, 256>>>();
    k_bnparam<<<4, 256>>>(gl[4], bl[4], 1.0f / (float)TOTALP, 1024);
    {
        dim3 g(NPTS / 32, 1024 / 32, 2);
        k_out<<<g, dim3(32, 8)>>>((float*)d_out);
    }
}